// round 14
// baseline (speedup 1.0000x reference)
#include <cuda_runtime.h>
#include <cuda_fp16.h>
#include <cstdint>

#define BM 128
#define BN 128
#define NST 64              // stages; 16 input features per stage
#define FEAT 16
#define SLOTS 144           // K-slots per stage (16 x 9) = 9 k16 steps exactly
#define ROWB 304            // SMEM row stride bytes (304 mod 128 = 48 -> conflict-free LDSM)
#define PLB (128*ROWB)      // 38912 per plane
#define BUFB (2*PLB)        // A, B = 77824
#define SMEM_TOT (2*BUFB)   // 155648
#define NTHR 384            // 8 compute warps (64x32) + 4 producer warps

// pre-expanded weights, stage-major fp16
__device__ __align__(16) __half g_b[(size_t)NST * 1024 * SLOTS];

static __device__ __forceinline__ uint32_t s2u(const void* p) {
    uint32_t a;
    asm("{ .reg .u64 t; cvta.to.shared.u64 t, %1; cvt.u32.u64 %0, t; }" : "=r"(a) : "l"(p));
    return a;
}
static __device__ __forceinline__ void cp16(uint32_t dst, const void* src) {
    asm volatile("cp.async.cg.shared.global [%0], [%1], 16;" :: "r"(dst), "l"(src));
}
static __device__ __forceinline__ void ldm4(uint32_t* r, uint32_t addr) {
    asm volatile("ldmatrix.sync.aligned.m8n8.x4.shared.b16 {%0,%1,%2,%3}, [%4];"
                 : "=r"(r[0]), "=r"(r[1]), "=r"(r[2]), "=r"(r[3]) : "r"(addr));
}
static __device__ __forceinline__ void mma16(float* c, const uint32_t* a,
                                             uint32_t b0, uint32_t b1) {
    asm volatile("mma.sync.aligned.m16n8k16.row.col.f32.f16.f16.f32 "
                 "{%0,%1,%2,%3}, {%4,%5,%6,%7}, {%8,%9}, {%0,%1,%2,%3};"
                 : "+f"(c[0]), "+f"(c[1]), "+f"(c[2]), "+f"(c[3])
                 : "r"(a[0]), "r"(a[1]), "r"(a[2]), "r"(a[3]), "r"(b0), "r"(b1));
}

// ---------------- prep: expand weights to fp16, stage-major ----------------
__global__ void wexp_kernel(const float* __restrict__ bw, const float* __restrict__ sw) {
    int n = blockIdx.x;      // output feature
    int s = threadIdx.x;     // stage (0..63)
    __half w[SLOTS];
    const float* bwr = bw + (size_t)n * 1024 + s * FEAT;
    const float* swr = sw + ((size_t)n * 1024 + (size_t)s * FEAT) * 8;
#pragma unroll
    for (int f = 0; f < FEAT; f++) {
        w[f * 9] = __float2half_rn(bwr[f]);
#pragma unroll
        for (int j = 0; j < 8; j++) w[f * 9 + 1 + j] = __float2half_rn(swr[f * 8 + j]);
    }
    uint4* d = (uint4*)(g_b + ((size_t)s * 1024 + n) * SLOTS);
#pragma unroll
    for (int j = 0; j < SLOTS / 8; j++) d[j] = ((uint4*)w)[j];
}

// ---------------- main fused GEMM (warp-specialized, pipelined fragments) ----------------
__global__ __launch_bounds__(NTHR, 1)
void kan_mma(const float* __restrict__ x, const float* __restrict__ gr,
             float* __restrict__ out) {
    extern __shared__ char smem[];
    __shared__ float s_g[4];   // kn0, kn11, invh

    const int tid  = threadIdx.x;
    const int lane = tid & 31, wid = tid >> 5;
    const int on0  = blockIdx.x * BN, bm0 = blockIdx.y * BM;
    const uint32_t sb = s2u(smem);

    if (tid == 0) {
        float k0 = gr[0], k1 = gr[1], k11 = gr[11];
        s_g[0] = k0; s_g[1] = k11; s_g[2] = 1.f / (k1 - k0);
    }
    __syncthreads();
    const float kn0 = s_g[0], kn11 = s_g[1], invh = s_g[2];

    if (wid >= 8) {
        // ======================= PRODUCER WARPS (128 threads) =======================
        const int row = tid - 256;                 // 0..127
        const __half* b_src = g_b + ((size_t)on0 + row) * SLOTS;
        const float* xrow = x + (size_t)(bm0 + row) * 1024;

        float4 xc[4], xn[4];

        auto loadX = [&](int s, float4* p) {
#pragma unroll
            for (int q = 0; q < 4; q++)
                p[q] = *(const float4*)(xrow + s * FEAT + q * 4);
        };
        auto issueB = [&](int s, int buf) {
            const size_t soff = (size_t)s * 1024 * SLOTS;
            uint32_t d = sb + buf * BUFB + PLB + row * ROWB;
#pragma unroll
            for (int j = 0; j < 18; j++) cp16(d + j * 16, b_src + soff + j * 8);
            asm volatile("cp.async.commit_group;" ::: "memory");
        };
        auto expandA = [&](int buf, const float4* xp) {
            char* abase = smem + buf * BUFB + row * ROWB;
            const float* xs = (const float*)xp;
            uint32_t arow[SLOTS / 2];
#pragma unroll
            for (int q = 0; q < SLOTS / 2; q++) arow[q] = 0u;
#pragma unroll
            for (int f = 0; f < FEAT; f++) {
                __half h = __float2half_rn(xs[f]);
                uint16_t uh; memcpy(&uh, &h, 2);
                int sl = f * 9;
                if (sl & 1) arow[sl >> 1] |= ((uint32_t)uh << 16);
                else        arow[sl >> 1] |= (uint32_t)uh;
            }
#pragma unroll
            for (int q = 0; q < SLOTS / 8; q++)
                *(uint4*)(abase + q * 16) = ((uint4*)arow)[q];
            // closed-form uniform cubic B-spline: 4 nonzero values, scattered
#pragma unroll
            for (int f = 0; f < FEAT; f++) {
                float v0 = xs[f];
                if (v0 >= kn0 && v0 < kn11) {
                    float u = (v0 - kn0) * invh;
                    float fi = floorf(u);
                    int i = (int)fi;
                    if (i > 10) { i = 10; fi = 10.f; }
                    float t = u - fi;
                    float omt = 1.f - t;
                    float t2 = t * t, t3 = t2 * t;
                    float B[4];
                    B[0] = omt * omt * omt * (1.f / 6.f);
                    B[1] = (3.f * t3 - 6.f * t2 + 4.f) * (1.f / 6.f);
                    B[2] = (-3.f * t3 + 3.f * t2 + 3.f * t + 1.f) * (1.f / 6.f);
                    B[3] = t3 * (1.f / 6.f);
                    int j0 = i - 3;
#pragma unroll
                    for (int k = 0; k < 4; k++) {
                        int j = j0 + k;
                        if (j >= 0 && j <= 7) {
                            __half hb = __float2half_rn(B[k]);
                            *(__half*)(abase + (f * 9 + 1 + j) * 2) = hb;
                        }
                    }
                }
            }
        };

        loadX(0, xc);
        issueB(0, 0);
        expandA(0, xc);
        loadX(1, xn);
        asm volatile("cp.async.wait_group 0;" ::: "memory");
        __syncthreads();                       // buf0 ready

        for (int s = 0; s < NST; ++s) {
            if (s + 1 < NST) {
                issueB(s + 1, (s + 1) & 1);
#pragma unroll
                for (int q = 0; q < 4; q++) xc[q] = xn[q];
                if (s + 2 < NST) loadX(s + 2, xn);
                expandA((s + 1) & 1, xc);
                asm volatile("cp.async.wait_group 0;" ::: "memory");
            }
            __syncthreads();                   // stage s consumed / s+1 ready
        }
    } else {
        // ======================= COMPUTE WARPS (256 threads) =======================
        const int wm = wid >> 2, wn = wid & 3;     // 2 x 4 warps, 64x32 tile each
        const int g = lane >> 2, t = lane & 3;

        const uint32_t a_off = (uint32_t)((((lane >> 3) & 1) * 8 + (lane & 7)) * ROWB + (lane >> 4) * 16);
        const uint32_t b_off = (uint32_t)(((lane >> 4) * 8 + (lane & 7)) * ROWB + ((lane >> 3) & 1) * 16);

        float acc[4][4][4];
#pragma unroll
        for (int mt = 0; mt < 4; mt++)
#pragma unroll
            for (int nt = 0; nt < 4; nt++)
#pragma unroll
                for (int r = 0; r < 4; r++) acc[mt][nt][r] = 0.f;

        uint32_t af[2][4][4], bf[2][8];   // double-buffered fragments

        __syncthreads();                       // wait buf0
        for (int s = 0; s < NST; ++s) {
            const uint32_t bo = sb + (s & 1) * BUFB;
            const uint32_t Ab = bo + wm * 64 * ROWB + a_off;
            const uint32_t Bb = bo + PLB + wn * 32 * ROWB + b_off;

            // preload kk=0 fragments
#pragma unroll
            for (int mt = 0; mt < 4; mt++)
                ldm4(af[0][mt], Ab + mt * 16 * ROWB);
            ldm4(bf[0],     Bb);
            ldm4(bf[0] + 4, Bb + 16 * ROWB);

#pragma unroll
            for (int kk = 0; kk < 9; kk++) {
                const int cur = kk & 1, nxt = cur ^ 1;
                if (kk < 8) {
                    const uint32_t kb = (kk + 1) * 32;
                    // issue next fragment loads FIRST; they drain while MMAs issue
                    ldm4(af[nxt][0], Ab + kb);
                    ldm4(af[nxt][1], Ab + 16 * ROWB + kb);
                    ldm4(bf[nxt],    Bb + kb);
                    ldm4(af[nxt][2], Ab + 32 * ROWB + kb);
                    ldm4(af[nxt][3], Ab + 48 * ROWB + kb);
                    ldm4(bf[nxt] + 4, Bb + 16 * ROWB + kb);
                }
#pragma unroll
                for (int mt = 0; mt < 4; mt++)
#pragma unroll
                    for (int nt = 0; nt < 4; nt++)
                        mma16(acc[mt][nt], af[cur][mt], bf[cur][2 * nt], bf[cur][2 * nt + 1]);
            }
            __syncthreads();
        }

        // ---- epilogue ----
#pragma unroll
        for (int mt = 0; mt < 4; mt++) {
#pragma unroll
            for (int nt = 0; nt < 4; nt++) {
                int r = bm0 + wm * 64 + mt * 16 + g;
                int c = on0 + wn * 32 + nt * 8 + 2 * t;
                *(float2*)(out + (size_t)r * 1024 + c)       = make_float2(acc[mt][nt][0], acc[mt][nt][1]);
                *(float2*)(out + (size_t)(r + 8) * 1024 + c) = make_float2(acc[mt][nt][2], acc[mt][nt][3]);
            }
        }
    }
}

extern "C" void kernel_launch(void* const* d_in, const int* in_sizes, int n_in,
                              void* d_out, int out_size) {
    const float* x  = (const float*)d_in[0];   // (8192, 1024)
    const float* bw = (const float*)d_in[1];   // (1024, 1024)
    const float* sw = (const float*)d_in[2];   // (1024, 1024, 8)
    const float* gr = (const float*)d_in[3];   // (1024, 12)
    float* out = (float*)d_out;                // (8192, 1024)

    cudaFuncSetAttribute(kan_mma, cudaFuncAttributeMaxDynamicSharedMemorySize, SMEM_TOT);
    wexp_kernel<<<1024, NST>>>(bw, sw);
    kan_mma<<<dim3(8, 64), NTHR, SMEM_TOT>>>(x, gr, out);
}

// round 15
// speedup vs baseline: 1.0181x; 1.0181x over previous
#include <cuda_runtime.h>
#include <cuda_fp16.h>
#include <cstdint>

#define BM 128
#define BN 128
#define NST 64              // stages; 16 input features per stage
#define FEAT 16
#define SLOTS 144           // K-slots per stage (16 x 9) = 9 k16 steps exactly
#define ROWB 304            // SMEM row stride bytes (304 mod 128 = 48 -> conflict-free LDSM)
#define PLB (128*ROWB)      // 38912 per plane
#define BUFB (2*PLB)        // A, B = 77824
#define SMEM_TOT (2*BUFB)   // 155648
#define NTHR 640            // 4 producer warps (wid 0-3) + 16 compute warps (wid 4-19, 32x32)

// pre-expanded weights, stage-major fp16
__device__ __align__(16) __half g_b[(size_t)NST * 1024 * SLOTS];

static __device__ __forceinline__ uint32_t s2u(const void* p) {
    uint32_t a;
    asm("{ .reg .u64 t; cvta.to.shared.u64 t, %1; cvt.u32.u64 %0, t; }" : "=r"(a) : "l"(p));
    return a;
}
static __device__ __forceinline__ void cp16(uint32_t dst, const void* src) {
    asm volatile("cp.async.cg.shared.global [%0], [%1], 16;" :: "r"(dst), "l"(src));
}
static __device__ __forceinline__ void ldm4(uint32_t* r, uint32_t addr) {
    asm volatile("ldmatrix.sync.aligned.m8n8.x4.shared.b16 {%0,%1,%2,%3}, [%4];"
                 : "=r"(r[0]), "=r"(r[1]), "=r"(r[2]), "=r"(r[3]) : "r"(addr));
}
static __device__ __forceinline__ void mma16(float* c, const uint32_t* a,
                                             uint32_t b0, uint32_t b1) {
    asm volatile("mma.sync.aligned.m16n8k16.row.col.f32.f16.f16.f32 "
                 "{%0,%1,%2,%3}, {%4,%5,%6,%7}, {%8,%9}, {%0,%1,%2,%3};"
                 : "+f"(c[0]), "+f"(c[1]), "+f"(c[2]), "+f"(c[3])
                 : "r"(a[0]), "r"(a[1]), "r"(a[2]), "r"(a[3]), "r"(b0), "r"(b1));
}

// ---------------- prep: expand weights to fp16, stage-major ----------------
__global__ void wexp_kernel(const float* __restrict__ bw, const float* __restrict__ sw) {
    int n = blockIdx.x;      // output feature
    int s = threadIdx.x;     // stage (0..63)
    __half w[SLOTS];
    const float* bwr = bw + (size_t)n * 1024 + s * FEAT;
    const float* swr = sw + ((size_t)n * 1024 + (size_t)s * FEAT) * 8;
#pragma unroll
    for (int f = 0; f < FEAT; f++) {
        w[f * 9] = __float2half_rn(bwr[f]);
#pragma unroll
        for (int j = 0; j < 8; j++) w[f * 9 + 1 + j] = __float2half_rn(swr[f * 8 + j]);
    }
    uint4* d = (uint4*)(g_b + ((size_t)s * 1024 + n) * SLOTS);
#pragma unroll
    for (int j = 0; j < SLOTS / 8; j++) d[j] = ((uint4*)w)[j];
}

// ---------------- main fused GEMM (warp-specialized, single-term fp16) ----------------
__global__ __launch_bounds__(NTHR, 1)
void kan_mma(const float* __restrict__ x, const float* __restrict__ gr,
             float* __restrict__ out) {
    extern __shared__ char smem[];
    __shared__ float s_g[4];   // kn0, kn11, invh

    const int tid  = threadIdx.x;
    const int lane = tid & 31, wid = tid >> 5;
    const int on0  = blockIdx.x * BN, bm0 = blockIdx.y * BM;
    const uint32_t sb = s2u(smem);

    if (tid == 0) {
        float k0 = gr[0], k1 = gr[1], k11 = gr[11];
        s_g[0] = k0; s_g[1] = k11; s_g[2] = 1.f / (k1 - k0);
    }
    __syncthreads();
    const float kn0 = s_g[0], kn11 = s_g[1], invh = s_g[2];

    if (wid < 4) {
        // ============== PRODUCER WARPS (128 threads, LOW wids = low priority) ==============
        const int row = tid;                       // 0..127
        const __half* b_src = g_b + ((size_t)on0 + row) * SLOTS;
        const float* xrow = x + (size_t)(bm0 + row) * 1024;

        float4 xc[4], xn[4];

        auto loadX = [&](int s, float4* p) {
#pragma unroll
            for (int q = 0; q < 4; q++)
                p[q] = *(const float4*)(xrow + s * FEAT + q * 4);
        };
        auto issueB = [&](int s, int buf) {
            const size_t soff = (size_t)s * 1024 * SLOTS;
            uint32_t d = sb + buf * BUFB + PLB + row * ROWB;
#pragma unroll
            for (int j = 0; j < 18; j++) cp16(d + j * 16, b_src + soff + j * 8);
            asm volatile("cp.async.commit_group;" ::: "memory");
        };
        auto expandA = [&](int buf, const float4* xp) {
            char* abase = smem + buf * BUFB + row * ROWB;
            const float* xs = (const float*)xp;
            uint32_t arow[SLOTS / 2];
#pragma unroll
            for (int q = 0; q < SLOTS / 2; q++) arow[q] = 0u;
#pragma unroll
            for (int f = 0; f < FEAT; f++) {
                __half h = __float2half_rn(xs[f]);
                uint16_t uh; memcpy(&uh, &h, 2);
                int sl = f * 9;
                if (sl & 1) arow[sl >> 1] |= ((uint32_t)uh << 16);
                else        arow[sl >> 1] |= (uint32_t)uh;
            }
#pragma unroll
            for (int q = 0; q < SLOTS / 8; q++)
                *(uint4*)(abase + q * 16) = ((uint4*)arow)[q];
            // closed-form uniform cubic B-spline: 4 nonzero values, scattered
#pragma unroll
            for (int f = 0; f < FEAT; f++) {
                float v0 = xs[f];
                if (v0 >= kn0 && v0 < kn11) {
                    float u = (v0 - kn0) * invh;
                    float fi = floorf(u);
                    int i = (int)fi;
                    if (i > 10) { i = 10; fi = 10.f; }
                    float t = u - fi;
                    float omt = 1.f - t;
                    float t2 = t * t, t3 = t2 * t;
                    float B[4];
                    B[0] = omt * omt * omt * (1.f / 6.f);
                    B[1] = (3.f * t3 - 6.f * t2 + 4.f) * (1.f / 6.f);
                    B[2] = (-3.f * t3 + 3.f * t2 + 3.f * t + 1.f) * (1.f / 6.f);
                    B[3] = t3 * (1.f / 6.f);
                    int j0 = i - 3;
#pragma unroll
                    for (int k = 0; k < 4; k++) {
                        int j = j0 + k;
                        if (j >= 0 && j <= 7) {
                            __half hb = __float2half_rn(B[k]);
                            *(__half*)(abase + (f * 9 + 1 + j) * 2) = hb;
                        }
                    }
                }
            }
        };

        loadX(0, xc);
        issueB(0, 0);
        expandA(0, xc);
        loadX(1, xn);
        asm volatile("cp.async.wait_group 0;" ::: "memory");
        __syncthreads();                       // buf0 ready

        for (int s = 0; s < NST; ++s) {
            if (s + 1 < NST) {
                issueB(s + 1, (s + 1) & 1);
#pragma unroll
                for (int q = 0; q < 4; q++) xc[q] = xn[q];
                if (s + 2 < NST) loadX(s + 2, xn);
                expandA((s + 1) & 1, xc);
                asm volatile("cp.async.wait_group 0;" ::: "memory");
            }
            __syncthreads();                   // stage s consumed / s+1 ready
        }
    } else {
        // ============== COMPUTE WARPS (512 threads, HIGH wids = arbiter priority) ==============
        const int cwid = wid - 4;                  // 0..15
        const int wm = cwid >> 2, wn = cwid & 3;   // 4 x 4 warps, 32x32 tile each
        const int g = lane >> 2, t = lane & 3;

        const uint32_t a_off = (uint32_t)((((lane >> 3) & 1) * 8 + (lane & 7)) * ROWB + (lane >> 4) * 16);
        const uint32_t b_off = (uint32_t)(((lane >> 4) * 8 + (lane & 7)) * ROWB + ((lane >> 3) & 1) * 16);

        float acc[2][4][4];
#pragma unroll
        for (int mt = 0; mt < 2; mt++)
#pragma unroll
            for (int nt = 0; nt < 4; nt++)
#pragma unroll
                for (int r = 0; r < 4; r++) acc[mt][nt][r] = 0.f;

        __syncthreads();                       // wait buf0
        for (int s = 0; s < NST; ++s) {
            const uint32_t bo = sb + (s & 1) * BUFB;
            const uint32_t Ab = bo + wm * 32 * ROWB + a_off;
            const uint32_t Bb = bo + PLB + wn * 32 * ROWB + b_off;

#pragma unroll
            for (int kk = 0; kk < 9; kk++) {
                const uint32_t kb = kk * 32;
                uint32_t a[2][4], b[8];
                ldm4(a[0], Ab + kb);
                ldm4(a[1], Ab + 16 * ROWB + kb);
                ldm4(b,     Bb + kb);
                ldm4(b + 4, Bb + 16 * ROWB + kb);
#pragma unroll
                for (int mt = 0; mt < 2; mt++)
#pragma unroll
                    for (int nt = 0; nt < 4; nt++)
                        mma16(acc[mt][nt], a[mt], b[2 * nt], b[2 * nt + 1]);
            }
            __syncthreads();
        }

        // ---- epilogue ----
#pragma unroll
        for (int mt = 0; mt < 2; mt++) {
#pragma unroll
            for (int nt = 0; nt < 4; nt++) {
                int r = bm0 + wm * 32 + mt * 16 + g;
                int c = on0 + wn * 32 + nt * 8 + 2 * t;
                *(float2*)(out + (size_t)r * 1024 + c)       = make_float2(acc[mt][nt][0], acc[mt][nt][1]);
                *(float2*)(out + (size_t)(r + 8) * 1024 + c) = make_float2(acc[mt][nt][2], acc[mt][nt][3]);
            }
        }
    }
}

extern "C" void kernel_launch(void* const* d_in, const int* in_sizes, int n_in,
                              void* d_out, int out_size) {
    const float* x  = (const float*)d_in[0];   // (8192, 1024)
    const float* bw = (const float*)d_in[1];   // (1024, 1024)
    const float* sw = (const float*)d_in[2];   // (1024, 1024, 8)
    const float* gr = (const float*)d_in[3];   // (1024, 12)
    float* out = (float*)d_out;                // (8192, 1024)

    cudaFuncSetAttribute(kan_mma, cudaFuncAttributeMaxDynamicSharedMemorySize, SMEM_TOT);
    wexp_kernel<<<1024, NST>>>(bw, sw);
    kan_mma<<<dim3(8, 64), NTHR, SMEM_TOT>>>(x, gr, out);
}

// round 16
// speedup vs baseline: 1.1711x; 1.1502x over previous
#include <cuda_runtime.h>
#include <cuda_fp16.h>
#include <cstdint>

#define BM 128
#define BN 128
#define NST 64              // stages; 16 input features per stage
#define FEAT 16
#define SLOTS 144           // K-slots per stage (16 x 9) = 9 k16 steps exactly
#define ROWB 304            // SMEM row stride bytes (304 mod 128 = 48 -> conflict-free LDSM)
#define PLB (128*ROWB)      // 38912 per plane
#define BUFB (2*PLB)        // A, B = 77824
#define SMEM_TOT (2*BUFB)   // 155648
#define NTHR 512            // 8 producer warps (wid 0-7) + 8 compute warps (wid 8-15, 64x32)

// pre-expanded weights, stage-major fp16
__device__ __align__(16) __half g_b[(size_t)NST * 1024 * SLOTS];

static __device__ __forceinline__ uint32_t s2u(const void* p) {
    uint32_t a;
    asm("{ .reg .u64 t; cvta.to.shared.u64 t, %1; cvt.u32.u64 %0, t; }" : "=r"(a) : "l"(p));
    return a;
}
static __device__ __forceinline__ void cp16(uint32_t dst, const void* src) {
    asm volatile("cp.async.cg.shared.global [%0], [%1], 16;" :: "r"(dst), "l"(src));
}
static __device__ __forceinline__ void ldm4(uint32_t* r, uint32_t addr) {
    asm volatile("ldmatrix.sync.aligned.m8n8.x4.shared.b16 {%0,%1,%2,%3}, [%4];"
                 : "=r"(r[0]), "=r"(r[1]), "=r"(r[2]), "=r"(r[3]) : "r"(addr));
}
static __device__ __forceinline__ void mma16(float* c, const uint32_t* a,
                                             uint32_t b0, uint32_t b1) {
    asm volatile("mma.sync.aligned.m16n8k16.row.col.f32.f16.f16.f32 "
                 "{%0,%1,%2,%3}, {%4,%5,%6,%7}, {%8,%9}, {%0,%1,%2,%3};"
                 : "+f"(c[0]), "+f"(c[1]), "+f"(c[2]), "+f"(c[3])
                 : "r"(a[0]), "r"(a[1]), "r"(a[2]), "r"(a[3]), "r"(b0), "r"(b1));
}
// split named barriers: ready[buf] = id 1+buf, free[buf] = id 3+buf; 512 participants
#define BAR_SYNC(id)   asm volatile("bar.sync %0, %1;"   :: "r"(id), "r"(NTHR) : "memory")
#define BAR_ARRIVE(id) asm volatile("bar.arrive %0, %1;" :: "r"(id), "r"(NTHR) : "memory")

// ---------------- prep: expand weights to fp16, stage-major ----------------
__global__ void wexp_kernel(const float* __restrict__ bw, const float* __restrict__ sw) {
    int n = blockIdx.x;      // output feature
    int s = threadIdx.x;     // stage (0..63)
    __half w[SLOTS];
    const float* bwr = bw + (size_t)n * 1024 + s * FEAT;
    const float* swr = sw + ((size_t)n * 1024 + (size_t)s * FEAT) * 8;
#pragma unroll
    for (int f = 0; f < FEAT; f++) {
        w[f * 9] = __float2half_rn(bwr[f]);
#pragma unroll
        for (int j = 0; j < 8; j++) w[f * 9 + 1 + j] = __float2half_rn(swr[f * 8 + j]);
    }
    uint4* d = (uint4*)(g_b + ((size_t)s * 1024 + n) * SLOTS);
#pragma unroll
    for (int j = 0; j < SLOTS / 8; j++) d[j] = ((uint4*)w)[j];
}

// ---------------- main fused GEMM (split-barrier warp specialization) ----------------
__global__ __launch_bounds__(NTHR, 1)
void kan_mma(const float* __restrict__ x, const float* __restrict__ gr,
             float* __restrict__ out) {
    extern __shared__ char smem[];
    __shared__ float s_g[4];   // kn0, kn11, invh

    const int tid  = threadIdx.x;
    const int lane = tid & 31, wid = tid >> 5;
    const int on0  = blockIdx.x * BN, bm0 = blockIdx.y * BM;
    const uint32_t sb = s2u(smem);

    if (tid == 0) {
        float k0 = gr[0], k1 = gr[1], k11 = gr[11];
        s_g[0] = k0; s_g[1] = k11; s_g[2] = 1.f / (k1 - k0);
    }
    __syncthreads();
    const float kn0 = s_g[0], kn11 = s_g[1], invh = s_g[2];

    if (wid < 8) {
        // ========== PRODUCER WARPS (256 threads: 2 per row, 8 features each) ==========
        const int row  = tid & 127;
        const int half = tid >> 7;                 // 0 or 1: features [half*8, half*8+8)
        const __half* b_src = g_b + ((size_t)on0 + row) * SLOTS + half * 72;
        const float*  xrow  = x + (size_t)(bm0 + row) * 1024 + half * 8;

        float4 xc0, xc1, xn0, xn1;

        auto loadX = [&](int s, float4& p0, float4& p1) {
            p0 = *(const float4*)(xrow + s * FEAT);
            p1 = *(const float4*)(xrow + s * FEAT + 4);
        };
        auto fill = [&](int s, const float4& p0, const float4& p1) {
            const int buf = s & 1;
            // B half-row via cp.async (9 x 16B)
            const size_t soff = (size_t)s * 1024 * SLOTS;
            uint32_t d = sb + buf * BUFB + PLB + row * ROWB + half * 144;
#pragma unroll
            for (int j = 0; j < 9; j++) cp16(d + j * 16, b_src + soff + j * 8);
            asm volatile("cp.async.commit_group;" ::: "memory");
            // A half-row: 8 features, 72 slots = 144 bytes
            float xs[8] = {p0.x, p0.y, p0.z, p0.w, p1.x, p1.y, p1.z, p1.w};
            char* abase = smem + buf * BUFB + row * ROWB + half * 144;
            uint32_t arow[36];
#pragma unroll
            for (int q = 0; q < 36; q++) arow[q] = 0u;
#pragma unroll
            for (int fl = 0; fl < 8; fl++) {
                __half h = __float2half_rn(xs[fl]);
                uint16_t uh; memcpy(&uh, &h, 2);
                int sl = fl * 9;
                if (sl & 1) arow[sl >> 1] |= ((uint32_t)uh << 16);
                else        arow[sl >> 1] |= (uint32_t)uh;
            }
#pragma unroll
            for (int q = 0; q < 9; q++)
                *(uint4*)(abase + q * 16) = ((uint4*)arow)[q];
            // closed-form uniform cubic B-spline, scatter 4 nonzeros
#pragma unroll
            for (int fl = 0; fl < 8; fl++) {
                float v0 = xs[fl];
                if (v0 >= kn0 && v0 < kn11) {
                    float u = (v0 - kn0) * invh;
                    float fi = floorf(u);
                    int i = (int)fi;
                    if (i > 10) { i = 10; fi = 10.f; }
                    float t = u - fi;
                    float omt = 1.f - t;
                    float t2 = t * t, t3 = t2 * t;
                    float B[4];
                    B[0] = omt * omt * omt * (1.f / 6.f);
                    B[1] = (3.f * t3 - 6.f * t2 + 4.f) * (1.f / 6.f);
                    B[2] = (-3.f * t3 + 3.f * t2 + 3.f * t + 1.f) * (1.f / 6.f);
                    B[3] = t3 * (1.f / 6.f);
                    int j0 = i - 3;
#pragma unroll
                    for (int k = 0; k < 4; k++) {
                        int j = j0 + k;
                        if (j >= 0 && j <= 7) {
                            __half hb = __float2half_rn(B[k]);
                            *(__half*)(abase + (fl * 9 + 1 + j) * 2) = hb;
                        }
                    }
                }
            }
            asm volatile("cp.async.wait_group 0;" ::: "memory");
        };

        loadX(0, xc0, xc1);
        loadX(1, xn0, xn1);
        for (int s = 0; s < NST; ++s) {
            if (s >= 2) BAR_SYNC(3 + (s & 1));      // wait buf free (compute arrived at s-2)
            fill(s, xc0, xc1);
            xc0 = xn0; xc1 = xn1;
            if (s + 2 < NST) loadX(s + 2, xn0, xn1);
            BAR_ARRIVE(1 + (s & 1));                // buf ready
        }
    } else {
        // ========== COMPUTE WARPS (256 threads, 2 x 4 warps, 64x32 tiles) ==========
        const int cwid = wid - 8;
        const int wm = cwid >> 2, wn = cwid & 3;
        const int g = lane >> 2, t = lane & 3;

        const uint32_t a_off = (uint32_t)((((lane >> 3) & 1) * 8 + (lane & 7)) * ROWB + (lane >> 4) * 16);
        const uint32_t b_off = (uint32_t)(((lane >> 4) * 8 + (lane & 7)) * ROWB + ((lane >> 3) & 1) * 16);

        float acc[4][4][4];
#pragma unroll
        for (int mt = 0; mt < 4; mt++)
#pragma unroll
            for (int nt = 0; nt < 4; nt++)
#pragma unroll
                for (int r = 0; r < 4; r++) acc[mt][nt][r] = 0.f;

        for (int s = 0; s < NST; ++s) {
            BAR_SYNC(1 + (s & 1));                  // wait buf ready
            const uint32_t bo = sb + (s & 1) * BUFB;
            const uint32_t Ab = bo + wm * 64 * ROWB + a_off;
            const uint32_t Bb = bo + PLB + wn * 32 * ROWB + b_off;

#pragma unroll
            for (int kk = 0; kk < 9; kk++) {
                const uint32_t kb = kk * 32;
                uint32_t a[4][4], b[8];
#pragma unroll
                for (int mt = 0; mt < 4; mt++)
                    ldm4(a[mt], Ab + mt * 16 * ROWB + kb);
                ldm4(b,     Bb + kb);
                ldm4(b + 4, Bb + 16 * ROWB + kb);
#pragma unroll
                for (int mt = 0; mt < 4; mt++)
#pragma unroll
                    for (int nt = 0; nt < 4; nt++)
                        mma16(acc[mt][nt], a[mt], b[2 * nt], b[2 * nt + 1]);
            }
            BAR_ARRIVE(3 + (s & 1));                // buf consumed
        }

        // ---- epilogue ----
#pragma unroll
        for (int mt = 0; mt < 4; mt++) {
#pragma unroll
            for (int nt = 0; nt < 4; nt++) {
                int r = bm0 + wm * 64 + mt * 16 + g;
                int c = on0 + wn * 32 + nt * 8 + 2 * t;
                *(float2*)(out + (size_t)r * 1024 + c)       = make_float2(acc[mt][nt][0], acc[mt][nt][1]);
                *(float2*)(out + (size_t)(r + 8) * 1024 + c) = make_float2(acc[mt][nt][2], acc[mt][nt][3]);
            }
        }
    }
}

extern "C" void kernel_launch(void* const* d_in, const int* in_sizes, int n_in,
                              void* d_out, int out_size) {
    const float* x  = (const float*)d_in[0];   // (8192, 1024)
    const float* bw = (const float*)d_in[1];   // (1024, 1024)
    const float* sw = (const float*)d_in[2];   // (1024, 1024, 8)
    const float* gr = (const float*)d_in[3];   // (1024, 12)
    float* out = (float*)d_out;                // (8192, 1024)

    cudaFuncSetAttribute(kan_mma, cudaFuncAttributeMaxDynamicSharedMemorySize, SMEM_TOT);
    wexp_kernel<<<1024, NST>>>(bw, sw);
    kan_mma<<<dim3(8, 64), NTHR, SMEM_TOT>>>(x, gr, out);
}